// round 8
// baseline (speedup 1.0000x reference)
#include <cuda_runtime.h>
#include <cuda_fp16.h>
#include <cstdint>
#include <math.h>

// Problem constants (fixed)
#define OUT_FEATURES 11008
#define IN_FEATURES  4096
#define TOKENS       64
#define BLOCK_SIZE   1024
#define W_ELEMS      (OUT_FEATURES * IN_FEATURES)     // 45,088,768 (fits int)
#define SEGS         (W_ELEMS / 64)                   // 704512
#define KSPLIT       2

// Scratch (device globals; no allocation allowed)
__device__ __half g_x[TOKENS * IN_FEATURES];          // x as fp16
__device__ int    g_qflag;                            // 0=int8, 1=int32, 2=float32
__device__ int    g_ocnt[SEGS + 1];                   // outliers before 64*seg
__device__ float  g_part[KSPLIT][TOKENS * OUT_FEATURES];

// ---------------------------------------------------------------------------
// Kernel 0: detect storage layout of int8_data (harness may upcast).
// ---------------------------------------------------------------------------
__global__ void detect_kernel(const void* __restrict__ qdata)
{
    __shared__ int c_i32, c_f32;
    if (threadIdx.x == 0) { c_i32 = 0; c_f32 = 0; }
    __syncthreads();
    const int t = threadIdx.x;   // 64 threads
    int w = ((const int*)qdata)[t];
    bool vi32 = (w >= -127 && w <= 127);
    float f = __int_as_float(w);
    bool vf32 = (!vi32) && isfinite(f) && fabsf(f) <= 127.0f && f == truncf(f);
    if (vi32) atomicAdd(&c_i32, 1);
    if (vf32) atomicAdd(&c_f32, 1);
    __syncthreads();
    if (t == 0) {
        int flag = 0;
        if (c_i32 >= 32) flag = 1;
        else if (c_f32 >= 32) flag = 2;
        g_qflag = flag;
    }
}

// ---------------------------------------------------------------------------
// Kernel 1: convert x (float32, fp16-exact) -> fp16 scratch.
// ---------------------------------------------------------------------------
__global__ void __launch_bounds__(256) convert_x_kernel(const float* __restrict__ x)
{
    const int i = blockIdx.x * blockDim.x + threadIdx.x;
    float4 f = ((const float4*)x)[i];
    __half2 h0 = __floats2half2_rn(f.x, f.y);
    __half2 h1 = __floats2half2_rn(f.z, f.w);
    uint2 p;
    p.x = *(unsigned*)&h0;
    p.y = *(unsigned*)&h1;
    ((uint2*)g_x)[i] = p;
}

// ---------------------------------------------------------------------------
// Kernel 2: g_ocnt[s] = #outliers with pos < 64*s, for s in [0, SEGS].
// ---------------------------------------------------------------------------
__global__ void __launch_bounds__(256) ocnt_kernel(
    const int* __restrict__ fp16_pos, int n_fp16)
{
    const int stride = gridDim.x * blockDim.x;
    for (int i = blockIdx.x * blockDim.x + threadIdx.x; i <= n_fp16; i += stride) {
        int lo = (i == 0) ? 0 : ((fp16_pos[i - 1] >> 6) + 1);
        int hi = (i == n_fp16) ? SEGS : (fp16_pos[i] >> 6);
        for (int s = lo; s <= hi; s++) g_ocnt[s] = i;
    }
}

// ---------------------------------------------------------------------------
// Fused dequant + split-K GEMM.
// grid (172, KSPLIT), 128 threads. Tile: 64M x 64N, K chunks of 64.
// ---------------------------------------------------------------------------
#define KC      64
#define KPS     (IN_FEATURES / KSPLIT)   // 2048
#define NKC     (KPS / KC)               // 32
#define SSTRIDE 72                       // halves per row in A/B tiles
#define A_HALVES (64 * SSTRIDE)          // 4608
#define RAWF    68                       // floats per row raw window (17 x 16B)
#define RAW_FLOATS (64 * RAWF)           // 4352

// smem layout (bytes)
#define SM_A    0                              // 2 stages * 9216
#define SM_RAW  (2 * A_HALVES * 2)             // 18432; 2 stages * 17408
#define SM_BT   (SM_RAW + 2 * RAW_FLOATS * 4)  // 53248; 9216
#define SM_META (SM_BT + A_HALVES * 2)         // 62464; 2 stages * 64 * int4
#define SM_TOTAL (SM_META + 2 * 64 * 16)       // 64512

__device__ __forceinline__ void cp_async16(void* smem_ptr, const void* gmem_ptr) {
    unsigned saddr = (unsigned)__cvta_generic_to_shared(smem_ptr);
    asm volatile("cp.async.cg.shared.global [%0], [%1], 16;\n" :: "r"(saddr), "l"(gmem_ptr));
}
// guarded: zero-fills bytes past src_size
__device__ __forceinline__ void cp_async16g(void* smem_ptr, const char* base,
                                            int off, int limit) {
    const char* src = base + off;
    int sz = 16;
    if (off + 16 > limit) {
        int rem = limit - off;
        sz = rem > 0 ? rem : 0;
        if (sz == 0) src = base;
    }
    unsigned saddr = (unsigned)__cvta_generic_to_shared(smem_ptr);
    asm volatile("cp.async.cg.shared.global [%0], [%1], 16, %2;\n"
                 :: "r"(saddr), "l"(src), "r"(sz));
}
__device__ __forceinline__ void cp_commit() {
    asm volatile("cp.async.commit_group;\n");
}
__device__ __forceinline__ void cp_wait0() {
    asm volatile("cp.async.wait_group 0;\n");
}

__global__ void __launch_bounds__(128) fused_gemm_kernel(
    const void*  __restrict__ qdata,
    const float* __restrict__ fp16_data,
    const float* __restrict__ scales,
    const int*   __restrict__ fp16_pos,
    int n_q)                                // ELEMENT count of qdata
{
    extern __shared__ char smem[];
    __half* As   = (__half*)(smem + SM_A);        // [2][A_HALVES]
    float*  RAW  = (float*)(smem + SM_RAW);       // [2][RAW_FLOATS]
    __half* BT   = (__half*)(smem + SM_BT);       // [64][SSTRIDE]
    int4*   META = (int4*)(smem + SM_META);       // [2][64]

    const int n0    = blockIdx.x * 64;
    const int kbase = blockIdx.y * KPS;
    const int t     = threadIdx.x;
    const int warp  = t >> 5;
    const int lane  = t & 31;
    const int g     = lane >> 2;
    const int tid4  = lane & 3;
    const int flag  = g_qflag;
    // FIX (round 7 bug): byte limit derived from the DETECTED element width,
    // not from in_sizes (which reports element count for any storage width).
    const int qlimit_bytes = (flag == 0) ? n_q : n_q * 4;

    const __half* X = g_x;
    const char*   qb = (const char*)qdata;

    // ---- stage loads for chunk kc into stage st ----
    auto load_stage = [&](int kc, int st) {
        const int k0 = kbase + kc * KC;
        __half* A = As + st * A_HALVES;
        #pragma unroll
        for (int q = 0; q < 4; q++) {
            const int idx = t + q * 128;
            const int row = idx >> 3;
            const int seg = idx & 7;
            cp_async16(A + row * SSTRIDE + seg * 8,
                       X + row * IN_FEATURES + k0 + seg * 8);
        }
        // B raw windows: 2 threads per row
        const int r  = t >> 1;
        const int p0 = (n0 + r) * IN_FEATURES + k0;
        const int sg = p0 >> 6;
        const int ob = g_ocnt[sg];
        const int oe = g_ocnt[sg + 1];
        const int cb = p0 - ob;
        float* rawrow = RAW + st * RAW_FLOATS + r * RAWF;
        if (flag == 0) {
            const int a0 = cb & ~15;
            if ((t & 1) == 0) {
                int4 m; m.x = cb - a0; m.y = oe - ob; m.z = ob;
                m.w = __float_as_int(scales[p0 >> 10]);
                META[st * 64 + r] = m;
            }
            for (int j = t & 1; j < 5; j += 2)
                cp_async16g((char*)rawrow + j * 16, qb, a0 + j * 16, qlimit_bytes);
        } else {
            const int a0 = cb & ~3;
            if ((t & 1) == 0) {
                int4 m; m.x = cb - a0; m.y = oe - ob; m.z = ob;
                m.w = __float_as_int(scales[p0 >> 10]);
                META[st * 64 + r] = m;
            }
            for (int j = t & 1; j < 17; j += 2)
                cp_async16g((char*)rawrow + j * 16, qb, a0 * 4 + j * 16, qlimit_bytes);
        }
        cp_commit();
    };

    float acc[8][4];
    #pragma unroll
    for (int n = 0; n < 8; n++)
        #pragma unroll
        for (int i = 0; i < 4; i++) acc[n][i] = 0.0f;

    load_stage(0, 0);

    for (int kc = 0; kc < NKC; kc++) {
        const int st = kc & 1;
        cp_wait0();
        __syncthreads();

        if (kc + 1 < NKC) load_stage(kc + 1, st ^ 1);

        // ---- convert raw[st] -> BT (fp16) ----
        {
            const int row = t >> 1;
            const int e0  = (t & 1) * 32;
            int4 m = META[st * 64 + row];
            const int   head = m.x;
            const int   cnt  = m.y;
            const int   ob   = m.z;
            const float sc   = __int_as_float(m.w);
            const float* rawrow = RAW + st * RAW_FLOATS + row * RAWF;
            __half* dst = BT + row * SSTRIDE + e0;

            if (cnt == 0) {
                if (flag == 2) {
                    #pragma unroll
                    for (int ee = 0; ee < 32; ee += 2) {
                        float v0 = rawrow[head + e0 + ee] * sc;
                        float v1 = rawrow[head + e0 + ee + 1] * sc;
                        *(__half2*)(dst + ee) = __floats2half2_rn(v0, v1);
                    }
                } else if (flag == 1) {
                    const int* ri = (const int*)rawrow;
                    #pragma unroll
                    for (int ee = 0; ee < 32; ee += 2) {
                        float v0 = (float)ri[head + e0 + ee] * sc;
                        float v1 = (float)ri[head + e0 + ee + 1] * sc;
                        *(__half2*)(dst + ee) = __floats2half2_rn(v0, v1);
                    }
                } else {
                    const int8_t* rb = (const int8_t*)rawrow;
                    #pragma unroll
                    for (int ee = 0; ee < 32; ee += 2) {
                        float v0 = (float)rb[head + e0 + ee] * sc;
                        float v1 = (float)rb[head + e0 + ee + 1] * sc;
                        *(__half2*)(dst + ee) = __floats2half2_rn(v0, v1);
                    }
                }
            } else {
                const int p0i = (n0 + row) * IN_FEATURES + kbase + kc * KC;
                int jj = 0, rank = 0;
                for (int ee = 0; ee < 32; ee += 2) {
                    float vv[2];
                    #pragma unroll
                    for (int u = 0; u < 2; u++) {
                        const int e = e0 + ee + u;
                        while (jj < cnt && (fp16_pos[ob + jj] - p0i) < e) { jj++; rank++; }
                        if (jj < cnt && (fp16_pos[ob + jj] - p0i) == e) {
                            vv[u] = fp16_data[ob + jj];
                        } else {
                            const int ci = head + e - rank;
                            float rv;
                            if (flag == 2)      rv = rawrow[ci];
                            else if (flag == 1) rv = (float)((const int*)rawrow)[ci];
                            else                rv = (float)((const int8_t*)rawrow)[ci];
                            vv[u] = rv * sc;
                        }
                    }
                    *(__half2*)(dst + ee) = __floats2half2_rn(vv[0], vv[1]);
                }
            }
        }
        __syncthreads();

        // ---- mma over A[st], BT ----
        const __half* A = As + st * A_HALVES;
        #pragma unroll
        for (int ks = 0; ks < 4; ks++) {
            const int kb = ks * 16;
            unsigned a0, a1, a2, a3;
            {
                const __half* p0 = A + (warp * 16 + g) * SSTRIDE + kb + tid4 * 2;
                const __half* p8 = A + (warp * 16 + g + 8) * SSTRIDE + kb + tid4 * 2;
                a0 = *(const unsigned*)p0;
                a2 = *(const unsigned*)(p0 + 8);
                a1 = *(const unsigned*)p8;
                a3 = *(const unsigned*)(p8 + 8);
            }
            #pragma unroll
            for (int n = 0; n < 8; n++) {
                const __half* pb = BT + (n * 8 + g) * SSTRIDE + kb + tid4 * 2;
                unsigned b0 = *(const unsigned*)pb;
                unsigned b1 = *(const unsigned*)(pb + 8);
                asm volatile(
                    "mma.sync.aligned.m16n8k16.row.col.f32.f16.f16.f32 "
                    "{%0,%1,%2,%3}, {%4,%5,%6,%7}, {%8,%9}, {%0,%1,%2,%3};\n"
                    : "+f"(acc[n][0]), "+f"(acc[n][1]), "+f"(acc[n][2]), "+f"(acc[n][3])
                    : "r"(a0), "r"(a1), "r"(a2), "r"(a3), "r"(b0), "r"(b1));
            }
        }
    }

    float* part = g_part[blockIdx.y];
    #pragma unroll
    for (int n = 0; n < 8; n++) {
        const int col = n0 + n * 8 + tid4 * 2;
        const int row0 = warp * 16 + g;
        const int row1 = row0 + 8;
        float2 o0 = make_float2(acc[n][0], acc[n][1]);
        float2 o1 = make_float2(acc[n][2], acc[n][3]);
        *(float2*)(part + row0 * OUT_FEATURES + col) = o0;
        *(float2*)(part + row1 * OUT_FEATURES + col) = o1;
    }
}

// ---------------------------------------------------------------------------
// Reduce split-K partials + bias (fp16-rounding mimic of reference).
// ---------------------------------------------------------------------------
__global__ void __launch_bounds__(256) reduce_kernel(
    const float* __restrict__ bias, float* __restrict__ out)
{
    const int i4 = blockIdx.x * blockDim.x + threadIdx.x;
    const int e0 = i4 * 4;
    const int col = e0 % OUT_FEATURES;

    float4 s  = *(const float4*)&g_part[0][e0];
    float4 s1 = *(const float4*)&g_part[1][e0];
    s.x += s1.x; s.y += s1.y; s.z += s1.z; s.w += s1.w;

    float4 bf = *(const float4*)(bias + col);

    float4 o;
    o.x = __half2float(__hadd(__float2half_rn(s.x), __float2half_rn(bf.x)));
    o.y = __half2float(__hadd(__float2half_rn(s.y), __float2half_rn(bf.y)));
    o.z = __half2float(__hadd(__float2half_rn(s.z), __float2half_rn(bf.z)));
    o.w = __half2float(__hadd(__float2half_rn(s.w), __float2half_rn(bf.w)));
    *(float4*)(out + e0) = o;
}

// ---------------------------------------------------------------------------
// Launch. Inputs: x, int8_data, fp16_data, scales, bias, int8_pos, fp16_pos,
// block_idx. int8_pos/block_idx unused by design.
// ---------------------------------------------------------------------------
extern "C" void kernel_launch(void* const* d_in, const int* in_sizes, int n_in,
                              void* d_out, int out_size)
{
    const float* x         = (const float*)d_in[0];
    const void*  int8_data = d_in[1];
    const float* fp16_data = (const float*)d_in[2];
    const float* scales    = (const float*)d_in[3];
    const float* bias      = (const float*)d_in[4];
    const int*   fp16_pos  = (const int*)d_in[6];
    const int    n_fp16    = in_sizes[2];
    const int    n_q       = in_sizes[1];   // element count

    detect_kernel<<<1, 64>>>(int8_data);
    convert_x_kernel<<<TOKENS * IN_FEATURES / (256 * 4), 256>>>(x);
    ocnt_kernel<<<256, 256>>>(fp16_pos, n_fp16);

    static bool attr_set = false;
    if (!attr_set) {
        cudaFuncSetAttribute(fused_gemm_kernel,
                             cudaFuncAttributeMaxDynamicSharedMemorySize, SM_TOTAL);
        attr_set = true;
    }
    fused_gemm_kernel<<<dim3(OUT_FEATURES / 64, KSPLIT), 128, SM_TOTAL>>>(
        int8_data, fp16_data, scales, fp16_pos, n_q);

    reduce_kernel<<<TOKENS * OUT_FEATURES / (256 * 4), 256>>>(bias, (float*)d_out);
}

// round 9
// speedup vs baseline: 2.3073x; 2.3073x over previous
#include <cuda_runtime.h>
#include <cuda_fp16.h>
#include <cstdint>
#include <math.h>

// Problem constants (fixed)
#define OUT_FEATURES 11008
#define IN_FEATURES  4096
#define TOKENS       64
#define BLOCK_SIZE   1024
#define NUM_BLOCKS   (OUT_FEATURES * IN_FEATURES / BLOCK_SIZE)   // 44032
#define W_ELEMS      (OUT_FEATURES * IN_FEATURES)                // 45,088,768
#define KSPLIT       4

// Scratch (device globals; no allocation allowed)
__device__ __half g_W[W_ELEMS];
__device__ __half g_x[TOKENS * IN_FEATURES];
__device__ int    g_qflag;                      // 0=int8, 1=int32, 2=float32
__device__ int    g_ostart[NUM_BLOCKS + 1];     // outlier lower_bound per 1024-block
__device__ float  g_part[KSPLIT][TOKENS * OUT_FEATURES];

// ---------------------------------------------------------------------------
// Kernel 0: detect storage layout of int8_data (harness may upcast).
// ---------------------------------------------------------------------------
__global__ void detect_kernel(const void* __restrict__ qdata)
{
    __shared__ int c_i32, c_f32;
    if (threadIdx.x == 0) { c_i32 = 0; c_f32 = 0; }
    __syncthreads();
    const int t = threadIdx.x;   // 64 threads
    int w = ((const int*)qdata)[t];
    bool vi32 = (w >= -127 && w <= 127);
    float f = __int_as_float(w);
    bool vf32 = (!vi32) && isfinite(f) && fabsf(f) <= 127.0f && f == truncf(f);
    if (vi32) atomicAdd(&c_i32, 1);
    if (vf32) atomicAdd(&c_f32, 1);
    __syncthreads();
    if (t == 0) {
        int flag = 0;
        if (c_i32 >= 32) flag = 1;
        else if (c_f32 >= 32) flag = 2;
        g_qflag = flag;
    }
}

// ---------------------------------------------------------------------------
// Kernel 1: convert x (float32, fp16-exact) -> fp16 scratch.
// ---------------------------------------------------------------------------
__global__ void __launch_bounds__(256) convert_x_kernel(const float* __restrict__ x)
{
    const int i = blockIdx.x * blockDim.x + threadIdx.x;
    float4 f = ((const float4*)x)[i];
    __half2 h0 = __floats2half2_rn(f.x, f.y);
    __half2 h1 = __floats2half2_rn(f.z, f.w);
    uint2 p;
    p.x = *(unsigned*)&h0;
    p.y = *(unsigned*)&h1;
    ((uint2*)g_x)[i] = p;
}

// ---------------------------------------------------------------------------
// Kernel 2: invert fp16_pos -> per-block outlier lower bounds.
// ---------------------------------------------------------------------------
__global__ void __launch_bounds__(256) ostart_kernel(
    const int* __restrict__ fp16_pos, int n_fp16)
{
    const int stride = gridDim.x * blockDim.x;
    for (int i = blockIdx.x * blockDim.x + threadIdx.x; i <= n_fp16; i += stride) {
        int lo = (i == 0) ? 0 : ((fp16_pos[i - 1] >> 10) + 1);
        int hi = (i == n_fp16) ? NUM_BLOCKS : (fp16_pos[i] >> 10);
        for (int b = lo; b <= hi; b++) g_ostart[b] = i;
    }
}

// ---------------------------------------------------------------------------
// Kernel 3: dequantize, input-centric. One CTA per 1024-elem quant block.
// Coalesced vector loads of the compact q-window; flat slot of the k-th
// non-outlier computed by insertion over the (tiny) ascending outlier list:
//   lp = k; for each outlier o ascending: lp += (o <= lp).
// Outlier values stored directly at their global positions.
// ---------------------------------------------------------------------------
__device__ __forceinline__ float4 load_q4(const void* qdata, int flag,
                                          int ci, int n_q)
{
    float4 r;
    if (flag == 2) {
        const float* q = (const float*)qdata;
        if (ci + 4 <= n_q) {
            r = *(const float4*)(q + ci);
        } else {
            r.x = (ci     < n_q) ? q[ci]     : 0.0f;
            r.y = (ci + 1 < n_q) ? q[ci + 1] : 0.0f;
            r.z = (ci + 2 < n_q) ? q[ci + 2] : 0.0f;
            r.w = (ci + 3 < n_q) ? q[ci + 3] : 0.0f;
        }
    } else if (flag == 1) {
        const int* q = (const int*)qdata;
        if (ci + 4 <= n_q) {
            int4 i4 = *(const int4*)(q + ci);
            r.x = (float)i4.x; r.y = (float)i4.y;
            r.z = (float)i4.z; r.w = (float)i4.w;
        } else {
            r.x = (ci     < n_q) ? (float)q[ci]     : 0.0f;
            r.y = (ci + 1 < n_q) ? (float)q[ci + 1] : 0.0f;
            r.z = (ci + 2 < n_q) ? (float)q[ci + 2] : 0.0f;
            r.w = (ci + 3 < n_q) ? (float)q[ci + 3] : 0.0f;
        }
    } else {
        const int8_t* q = (const int8_t*)qdata;
        if (ci + 4 <= n_q) {
            uchar4 u = *(const uchar4*)(q + ci);
            r.x = (float)(int8_t)u.x; r.y = (float)(int8_t)u.y;
            r.z = (float)(int8_t)u.z; r.w = (float)(int8_t)u.w;
        } else {
            r.x = (ci     < n_q) ? (float)q[ci]     : 0.0f;
            r.y = (ci + 1 < n_q) ? (float)q[ci + 1] : 0.0f;
            r.z = (ci + 2 < n_q) ? (float)q[ci + 2] : 0.0f;
            r.w = (ci + 3 < n_q) ? (float)q[ci + 3] : 0.0f;
        }
    }
    return r;
}

__global__ void __launch_bounds__(128) dequant_kernel(
    const void*  __restrict__ qdata,
    const float* __restrict__ fp16_data,
    const float* __restrict__ scales,
    const int*   __restrict__ fp16_pos,
    int n_q)
{
    __shared__ int s_op[1024];     // local outlier positions (ascending)

    const int b    = blockIdx.x;
    const int t    = threadIdx.x;
    const int base = b << 10;

    const int o_s  = g_ostart[b];
    const int o_e  = g_ostart[b + 1];
    const int cnt  = o_e - o_s;
    const int cb   = base - o_s;          // compact index of block's first int8
    const int len  = BLOCK_SIZE - cnt;
    const int flag = g_qflag;
    const float sc = scales[b];

    // stage outlier local positions + write outlier values directly
    for (int i = t; i < cnt; i += 128) {
        const int p = fp16_pos[o_s + i];
        s_op[i] = p - base;
        g_W[p] = __float2half_rn(fp16_data[o_s + i]);
    }
    __syncthreads();

    const int a0   = cb & ~3;
    const int head = cb - a0;             // 0..3
    (void)head;

    // two vectorized groups + small tail (threads 0,1 cover [1024,1032))
    float v[8];
    int   k0[2];
    {
        const int ciA = a0 + 4 * t;
        const int ciB = a0 + 512 + 4 * t;
        float4 ra = load_q4(qdata, flag, ciA, n_q);
        float4 rb = load_q4(qdata, flag, ciB, n_q);
        v[0] = ra.x; v[1] = ra.y; v[2] = ra.z; v[3] = ra.w;
        v[4] = rb.x; v[5] = rb.y; v[6] = rb.z; v[7] = rb.w;
        k0[0] = ciA - cb;                 // non-outlier rank of v[0]
        k0[1] = ciB - cb;
    }

    // insertion: lp starts at k, bumped past every outlier at or before it
    int lp[8];
    #pragma unroll
    for (int s = 0; s < 8; s++) lp[s] = k0[s >> 2] + (s & 3);
    for (int j = 0; j < cnt; j++) {
        const int o = s_op[j];
        #pragma unroll
        for (int s = 0; s < 8; s++) lp[s] += (o <= lp[s]) ? 1 : 0;
    }

    #pragma unroll
    for (int s = 0; s < 8; s++) {
        const int k = k0[s >> 2] + (s & 3);
        if ((unsigned)k < (unsigned)len)
            g_W[base + lp[s]] = __float2half_rn(v[s] * sc);
    }

    // tail: compact indices [a0+1024, a0+1032) (covers head>cnt overhang)
    if (t < 2) {
        const int ciT = a0 + 1024 + 4 * t;
        float4 rt = load_q4(qdata, flag, ciT, n_q);
        float vt[4] = {rt.x, rt.y, rt.z, rt.w};
        #pragma unroll
        for (int s = 0; s < 4; s++) {
            const int k = ciT + s - cb;
            if ((unsigned)k < (unsigned)len) {
                int l = k;
                for (int j = 0; j < cnt; j++) l += (s_op[j] <= l) ? 1 : 0;
                g_W[base + l] = __float2half_rn(vt[s] * sc);
            }
        }
    }
}

// ---------------------------------------------------------------------------
// Kernel 4: split-K GEMM (round-5 proven). grid (172, KSPLIT). 64M x 64N,
// K range 1024, chunks of 64, 3-stage cp.async, mma.sync m16n8k16.
// ---------------------------------------------------------------------------
#define KC      64
#define KPS     (IN_FEATURES / KSPLIT)   // 1024 per split
#define NKC     (KPS / KC)               // 16 chunks
#define STAGES  3
#define SSTRIDE 72
#define STAGE_HALVES (64 * SSTRIDE)      // 4608

__device__ __forceinline__ void cp_async16(void* smem_ptr, const void* gmem_ptr) {
    unsigned saddr = (unsigned)__cvta_generic_to_shared(smem_ptr);
    asm volatile("cp.async.cg.shared.global [%0], [%1], 16;\n" :: "r"(saddr), "l"(gmem_ptr));
}
__device__ __forceinline__ void cp_commit() {
    asm volatile("cp.async.commit_group;\n");
}
template <int N>
__device__ __forceinline__ void cp_wait() {
    asm volatile("cp.async.wait_group %0;\n" :: "n"(N));
}

__global__ void __launch_bounds__(128) gemm_kernel()
{
    extern __shared__ __half smem[];
    __half* As = smem;
    __half* Bs = smem + STAGES * STAGE_HALVES;

    const int n0    = blockIdx.x * 64;
    const int kbase = blockIdx.y * KPS;
    const int t     = threadIdx.x;
    const int warp  = t >> 5;
    const int lane  = t & 31;
    const int g     = lane >> 2;
    const int tid4  = lane & 3;

    const __half* X = g_x;
    const __half* W = g_W;

    auto load_stage = [&](int kc, int st) {
        const int k0 = kbase + kc * KC;
        __half* A = As + st * STAGE_HALVES;
        __half* B = Bs + st * STAGE_HALVES;
        #pragma unroll
        for (int q = 0; q < 4; q++) {
            const int idx = t + q * 128;
            const int row = idx >> 3;
            const int seg = idx & 7;
            cp_async16(A + row * SSTRIDE + seg * 8,
                       X + row * IN_FEATURES + k0 + seg * 8);
            cp_async16(B + row * SSTRIDE + seg * 8,
                       W + (long)(n0 + row) * IN_FEATURES + k0 + seg * 8);
        }
        cp_commit();
    };

    float acc[8][4];
    #pragma unroll
    for (int n = 0; n < 8; n++)
        #pragma unroll
        for (int i = 0; i < 4; i++) acc[n][i] = 0.0f;

    load_stage(0, 0);
    load_stage(1, 1);

    for (int kc = 0; kc < NKC; kc++) {
        const int st = kc % STAGES;
        if (kc == NKC - 1) cp_wait<0>(); else cp_wait<1>();
        __syncthreads();

        if (kc + 2 < NKC) load_stage(kc + 2, (kc + 2) % STAGES);

        const __half* A = As + st * STAGE_HALVES;
        const __half* B = Bs + st * STAGE_HALVES;

        #pragma unroll
        for (int ks = 0; ks < 4; ks++) {
            const int kb = ks * 16;
            unsigned a0, a1, a2, a3;
            {
                const __half* p0 = A + (warp * 16 + g) * SSTRIDE + kb + tid4 * 2;
                const __half* p8 = A + (warp * 16 + g + 8) * SSTRIDE + kb + tid4 * 2;
                a0 = *(const unsigned*)p0;
                a2 = *(const unsigned*)(p0 + 8);
                a1 = *(const unsigned*)p8;
                a3 = *(const unsigned*)(p8 + 8);
            }
            #pragma unroll
            for (int n = 0; n < 8; n++) {
                const __half* pb = B + (n * 8 + g) * SSTRIDE + kb + tid4 * 2;
                unsigned b0 = *(const unsigned*)pb;
                unsigned b1 = *(const unsigned*)(pb + 8);
                asm volatile(
                    "mma.sync.aligned.m16n8k16.row.col.f32.f16.f16.f32 "
                    "{%0,%1,%2,%3}, {%4,%5,%6,%7}, {%8,%9}, {%0,%1,%2,%3};\n"
                    : "+f"(acc[n][0]), "+f"(acc[n][1]), "+f"(acc[n][2]), "+f"(acc[n][3])
                    : "r"(a0), "r"(a1), "r"(a2), "r"(a3), "r"(b0), "r"(b1));
            }
        }
        __syncthreads();
    }

    float* part = g_part[blockIdx.y];
    #pragma unroll
    for (int n = 0; n < 8; n++) {
        const int col = n0 + n * 8 + tid4 * 2;
        const int row0 = warp * 16 + g;
        const int row1 = row0 + 8;
        float2 o0 = make_float2(acc[n][0], acc[n][1]);
        float2 o1 = make_float2(acc[n][2], acc[n][3]);
        *(float2*)(part + row0 * OUT_FEATURES + col) = o0;
        *(float2*)(part + row1 * OUT_FEATURES + col) = o1;
    }
}

// ---------------------------------------------------------------------------
// Kernel 5: reduce split-K partials + bias (fp16-rounding mimic of reference).
// ---------------------------------------------------------------------------
__global__ void __launch_bounds__(256) reduce_kernel(
    const float* __restrict__ bias, float* __restrict__ out)
{
    const int i4 = blockIdx.x * blockDim.x + threadIdx.x;
    const int e0 = i4 * 4;
    const int col = e0 % OUT_FEATURES;

    float4 s  = *(const float4*)&g_part[0][e0];
    float4 s1 = *(const float4*)&g_part[1][e0];
    float4 s2 = *(const float4*)&g_part[2][e0];
    float4 s3 = *(const float4*)&g_part[3][e0];
    s.x += s1.x + s2.x + s3.x;
    s.y += s1.y + s2.y + s3.y;
    s.z += s1.z + s2.z + s3.z;
    s.w += s1.w + s2.w + s3.w;

    float4 bf = *(const float4*)(bias + col);

    float4 o;
    o.x = __half2float(__hadd(__float2half_rn(s.x), __float2half_rn(bf.x)));
    o.y = __half2float(__hadd(__float2half_rn(s.y), __float2half_rn(bf.y)));
    o.z = __half2float(__hadd(__float2half_rn(s.z), __float2half_rn(bf.z)));
    o.w = __half2float(__hadd(__float2half_rn(s.w), __float2half_rn(bf.w)));
    *(float4*)(out + e0) = o;
}

// ---------------------------------------------------------------------------
// Launch. Inputs: x, int8_data, fp16_data, scales, bias, int8_pos, fp16_pos,
// block_idx. int8_pos/block_idx unused by design.
// ---------------------------------------------------------------------------
extern "C" void kernel_launch(void* const* d_in, const int* in_sizes, int n_in,
                              void* d_out, int out_size)
{
    const float* x         = (const float*)d_in[0];
    const void*  int8_data = d_in[1];
    const float* fp16_data = (const float*)d_in[2];
    const float* scales    = (const float*)d_in[3];
    const float* bias      = (const float*)d_in[4];
    const int*   fp16_pos  = (const int*)d_in[6];
    const int    n_fp16    = in_sizes[2];
    const int    n_q       = in_sizes[1];   // element count

    detect_kernel<<<1, 64>>>(int8_data);
    convert_x_kernel<<<TOKENS * IN_FEATURES / (256 * 4), 256>>>(x);
    ostart_kernel<<<256, 256>>>(fp16_pos, n_fp16);
    dequant_kernel<<<NUM_BLOCKS, 128>>>(int8_data, fp16_data, scales, fp16_pos, n_q);

    const int smem_bytes = 2 * STAGES * STAGE_HALVES * (int)sizeof(__half); // 55296
    static bool attr_set = false;
    if (!attr_set) {
        cudaFuncSetAttribute(gemm_kernel,
                             cudaFuncAttributeMaxDynamicSharedMemorySize, smem_bytes);
        attr_set = true;
    }
    gemm_kernel<<<dim3(OUT_FEATURES / 64, KSPLIT), 128, smem_bytes>>>();

    reduce_kernel<<<TOKENS * OUT_FEATURES / (256 * 4), 256>>>(bias, (float*)d_out);
}